// round 13
// baseline (speedup 1.0000x reference)
#include <cuda_runtime.h>

#define N_CHROM 23
#define BINS    5000
#define NB      16
#define NS      512
#define EOS_DIM 512
#define BIN_DIM 256
#define VOCAB   (N_CHROM * BINS)        // 115000
#define NSAMP   (N_CHROM * NB * NS)     // 188416
#define NQUAD   (NSAMP / 4)             // 47104
#define OCC     3
#define GRID    (148 * OCC)             // 444
#define NWARPS  (GRID * 8)              // 3552
#define EOS_B0  (GRID - 46)             // eos handled by high block ids (398..443)
#define CWARPS  1797                    // 64-row chunks: 1797*64 >= 115000

// ---- scratch (device globals) ----
__device__ float    g_M[3 * BIN_DIM];      // W_fc1 @ W_bin  [3,256]
__device__ float    g_Meos[3 * EOS_DIM];   // W_fc2 @ W_eos  [3,512]
__device__ float    g_cbias[4];
__device__ float4   g_E[NB * N_CHROM];
__device__ float4   g_P[VOCAB];
__device__ unsigned char g_flag[VOCAB];    // row-needed flags (idempotent set)
__device__ int      g_chunkcnt[CWARPS];    // per-64-row-chunk needed counts
__device__ int      g_list[VOCAB + 2];     // SORTED compacted needed-row indices
__device__ int      g_cnt;                 // total needed rows (overwritten each launch)
__device__ unsigned g_bar;                 // monotone barrier counter (zero-init)

__device__ __forceinline__ void grid_bar(unsigned target) {
    __syncthreads();
    if (threadIdx.x == 0) {
        __threadfence();
        unsigned prev = atomicAdd(&g_bar, 1u);
        if (prev + 1u < target) {
            while (*(volatile unsigned*)&g_bar < target) __nanosleep(32);
        }
        __threadfence();
    }
    __syncthreads();
}

__device__ __forceinline__ float dot8(float4 a, float4 b, float4 m, float4 mb) {
    return a.x*m.x + a.y*m.y + a.z*m.z + a.w*m.w
         + b.x*mb.x + b.y*mb.y + b.z*mb.z + b.w*mb.w;
}

__global__ void __launch_bounds__(256, OCC)
k_fused(const float*  __restrict__ eos_emb,   // [16,23,512]
        const int4*   __restrict__ sampled,   // [23,16,512] as quads
        const int4*   __restrict__ targets,
        const float4* __restrict__ tbl,       // [115000,64] float4
        const float*  __restrict__ Wbin,      // [512,256]
        const float*  __restrict__ Weos,      // [512,512]
        const float*  __restrict__ beos,      // [512]
        const float*  __restrict__ Wfc,       // [3,1024]
        const float*  __restrict__ bfc,       // [3]
        float* __restrict__ out,
        int write_targets) {
    const int bid  = blockIdx.x;
    const int tid  = threadIdx.x;
    const int lane = tid & 31;
    const int warp = tid >> 5;
    const int gw   = bid * 8 + warp;

    __shared__ float  s[3][8][32];
    __shared__ float4 sM[3 * 64];

    // ================= Phase 0: prep + flags =================
    if (bid < 24) {
        bool is_eos = (bid < 16);
        int  e      = (is_eos ? bid * 32 : (bid - 16) * 32) + lane;
        int  stride = is_eos ? 512 : 256;
        const float* W = is_eos ? Weos : Wbin;
        int  fc     = is_eos ? 512 : 0;

        float a0 = 0.f, a1 = 0.f, a2 = 0.f;
        int dbeg = warp * 64;
#pragma unroll 16
        for (int d = dbeg; d < dbeg + 64; d++) {
            float w = W[d * stride + e];
            a0 += __ldg(&Wfc[fc + d])        * w;
            a1 += __ldg(&Wfc[1024 + fc + d]) * w;
            a2 += __ldg(&Wfc[2048 + fc + d]) * w;
        }
        s[0][warp][lane] = a0;
        s[1][warp][lane] = a1;
        s[2][warp][lane] = a2;
        __syncthreads();
#pragma unroll
        for (int off = 4; off; off >>= 1) {
            if (warp < off) {
                s[0][warp][lane] += s[0][warp + off][lane];
                s[1][warp][lane] += s[1][warp + off][lane];
                s[2][warp][lane] += s[2][warp + off][lane];
            }
            __syncthreads();
        }
        if (warp == 0) {
            if (is_eos) {
                g_Meos[e]        = s[0][0][lane];
                g_Meos[512 + e]  = s[1][0][lane];
                g_Meos[1024 + e] = s[2][0][lane];
            } else {
                g_M[e]           = s[0][0][lane];
                g_M[256 + e]     = s[1][0][lane];
                g_M[512 + e]     = s[2][0][lane];
            }
        }
    } else {
        if (bid == 24 && tid < 32) {
            float a0 = 0.f, a1 = 0.f, a2 = 0.f;
#pragma unroll
            for (int d = lane; d < 512; d += 32) {
                float v = beos[d];
                a0 += Wfc[512 + d]        * v;
                a1 += Wfc[1024 + 512 + d] * v;
                a2 += Wfc[2048 + 512 + d] * v;
            }
#pragma unroll
            for (int o = 16; o; o >>= 1) {
                a0 += __shfl_down_sync(0xffffffffu, a0, o);
                a1 += __shfl_down_sync(0xffffffffu, a1, o);
                a2 += __shfl_down_sync(0xffffffffu, a2, o);
            }
            if (lane == 0) {
                g_cbias[0] = a0 + bfc[0];
                g_cbias[1] = a1 + bfc[1];
                g_cbias[2] = a2 + bfc[2];
            }
        }
        // ---- row-needed flags: idempotent writes, identical every launch ----
        if (bid >= 25) {
            int q = (bid - 25) * 113 + tid;     // 419 blocks x 113 >= 47104
            if (tid < 113 && q < NQUAD) {
                int i = q * 4;
                int c = i / (NB * NS);
                int4 sv = sampled[q];
                int vb = c * BINS;
                g_flag[vb + sv.x] = 1;
                g_flag[vb + sv.y] = 1;
                g_flag[vb + sv.z] = 1;
                g_flag[vb + sv.w] = 1;
            }
        }
    }

    grid_bar(GRID);   // ---- barrier A: g_M / g_Meos / g_cbias / g_flag ready ----

    if (tid < 192) sM[tid] = reinterpret_cast<const float4*>(g_M)[tid];
    __syncthreads();

    // ============ Phase 1a: per-chunk counts (+ eos on high blocks) ========
    if (gw < CWARPS) {
        int base = gw * 64;
        int i1 = base + lane, i2 = base + 32 + lane;
        bool f1 = (i1 < VOCAB) && g_flag[i1];
        bool f2 = (i2 < VOCAB) && g_flag[i2];
        unsigned b1 = __ballot_sync(0xffffffffu, f1);
        unsigned b2 = __ballot_sync(0xffffffffu, f2);
        if (lane == 0) g_chunkcnt[gw] = __popc(b1) + __popc(b2);
    }
    if (bid >= EOS_B0) {
        int w = (bid - EOS_B0) * 8 + warp;   // 0..367 = b*23 + c
        const float4* row = reinterpret_cast<const float4*>(eos_emb + (size_t)w * EOS_DIM);
        const float4* M0  = reinterpret_cast<const float4*>(g_Meos);
        const float4* M1  = reinterpret_cast<const float4*>(g_Meos + EOS_DIM);
        const float4* M2  = reinterpret_cast<const float4*>(g_Meos + 2 * EOS_DIM);
        float s0 = 0.f, s1 = 0.f, s2 = 0.f;
#pragma unroll
        for (int i = lane; i < EOS_DIM / 4; i += 32) {
            float4 x = row[i];
            float4 m0 = M0[i], m1 = M1[i], m2 = M2[i];
            s0 += x.x*m0.x + x.y*m0.y + x.z*m0.z + x.w*m0.w;
            s1 += x.x*m1.x + x.y*m1.y + x.z*m1.z + x.w*m1.w;
            s2 += x.x*m2.x + x.y*m2.y + x.z*m2.z + x.w*m2.w;
        }
#pragma unroll
        for (int o = 16; o; o >>= 1) {
            s0 += __shfl_down_sync(0xffffffffu, s0, o);
            s1 += __shfl_down_sync(0xffffffffu, s1, o);
            s2 += __shfl_down_sync(0xffffffffu, s2, o);
        }
        if (lane == 0)
            g_E[w] = make_float4(s0 + g_cbias[0], s1 + g_cbias[1], s2 + g_cbias[2], 0.f);
    }

    grid_bar(2 * GRID);   // ---- barrier A2: counts / g_E ready ----

    // ============ Phase 1b: SORTED scatter (per-warp prefix, no scan pass) ==
    if (gw < CWARPS) {
        // exclusive prefix of counts[0..gw): strided sum, L2-resident (7 KB)
        int acc = 0;
        for (int i = lane; i < gw; i += 32) acc += g_chunkcnt[i];
#pragma unroll
        for (int o = 16; o; o >>= 1) acc += __shfl_xor_sync(0xffffffffu, acc, o);
        // re-ballot and scatter in ascending order
        int base = gw * 64;
        int i1 = base + lane, i2 = base + 32 + lane;
        bool f1 = (i1 < VOCAB) && g_flag[i1];
        bool f2 = (i2 < VOCAB) && g_flag[i2];
        unsigned b1 = __ballot_sync(0xffffffffu, f1);
        unsigned b2 = __ballot_sync(0xffffffffu, f2);
        int n1 = __popc(b1);
        unsigned lt = (1u << lane) - 1u;
        if (f1) g_list[acc + __popc(b1 & lt)] = i1;
        if (f2) g_list[acc + n1 + __popc(b2 & lt)] = i2;
        if (gw == CWARPS - 1 && lane == 0)
            g_cnt = acc + n1 + __popc(b2);
    }

    grid_bar(3 * GRID);   // ---- barrier B: g_list / g_cnt ready ----

    // ===== Phase 2: compacted SORTED sweep (uniform, pipelined, __ldcs) =====
    {
        const int  total  = g_cnt;
        const int  nunits = (total + 1) >> 1;
        const int2* Lp = reinterpret_cast<const int2*>(g_list);

        int u = gw;
        if (u < nunits) {
            int2 vv = Lp[u];
            int v0 = vv.x;
            int v1 = (2 * u + 1 < total) ? vv.y : vv.x;
            const float4* r0p = tbl + (size_t)v0 * 64;
            const float4* r1p = tbl + (size_t)v1 * 64;
            float4 A0 = __ldcs(r0p + lane);
            float4 A1 = __ldcs(r0p + 32 + lane);
            float4 A2 = __ldcs(r1p + lane);
            float4 A3 = __ldcs(r1p + 32 + lane);

            while (true) {
                int  un   = u + NWARPS;
                bool more = un < nunits;
                int w0, w1;
                float4 B0, B1, B2, B3;
                if (more) {
                    int2 nv = Lp[un];
                    w0 = nv.x;
                    w1 = (2 * un + 1 < total) ? nv.y : nv.x;
                    const float4* n0 = tbl + (size_t)w0 * 64;
                    const float4* n1 = tbl + (size_t)w1 * 64;
                    B0 = __ldcs(n0 + lane);
                    B1 = __ldcs(n0 + 32 + lane);
                    B2 = __ldcs(n1 + lane);
                    B3 = __ldcs(n1 + 32 + lane);
                }
                // ---- row v0 ----
                float r0 = dot8(A0, A1, sM[lane],       sM[32 + lane]);
                float r1 = dot8(A0, A1, sM[64 + lane],  sM[96 + lane]);
                float r2 = dot8(A0, A1, sM[128 + lane], sM[160 + lane]);
#pragma unroll
                for (int o = 16; o; o >>= 1) {
                    r0 += __shfl_xor_sync(0xffffffffu, r0, o);
                    r1 += __shfl_xor_sync(0xffffffffu, r1, o);
                    r2 += __shfl_xor_sync(0xffffffffu, r2, o);
                }
                // ---- row v1 ----
                float t0 = dot8(A2, A3, sM[lane],       sM[32 + lane]);
                float t1 = dot8(A2, A3, sM[64 + lane],  sM[96 + lane]);
                float t2 = dot8(A2, A3, sM[128 + lane], sM[160 + lane]);
#pragma unroll
                for (int o = 16; o; o >>= 1) {
                    t0 += __shfl_xor_sync(0xffffffffu, t0, o);
                    t1 += __shfl_xor_sync(0xffffffffu, t1, o);
                    t2 += __shfl_xor_sync(0xffffffffu, t2, o);
                }
                if (lane < 2) {
                    int    dst = (lane == 0) ? v0 : v1;
                    float4 val = (lane == 0) ? make_float4(r0, r1, r2, 0.f)
                                             : make_float4(t0, t1, t2, 0.f);
                    g_P[dst] = val;
                }
                if (!more) break;
                A0 = B0; A1 = B1; A2 = B2; A3 = B3;
                v0 = w0; v1 = w1;
                u = un;
            }
        }
    }

    grid_bar(4 * GRID);   // ---- barrier C: g_P ready ----

    // ================= Phase 3: gather + relu + emit ==================
    {
        int q = bid * 107 + tid;                 // 107 quads/block, coalesced
        if (tid < 107 && q < NQUAD) {
            int i = q * 4;
            int c = i / (NB * NS);
            int b = (i - c * (NB * NS)) / NS;

            int4 sv = sampled[q];
            int  vb = c * BINS;
            float4 p0 = g_P[vb + sv.x];
            float4 p1 = g_P[vb + sv.y];
            float4 p2 = g_P[vb + sv.z];
            float4 p3 = g_P[vb + sv.w];
            float4 e  = g_E[b * N_CHROM + c];

            float4* o4 = reinterpret_cast<float4*>(out + 12 * (size_t)q);
            o4[0] = make_float4(fmaxf(p0.x + e.x, 0.f), fmaxf(p0.y + e.y, 0.f),
                                fmaxf(p0.z + e.z, 0.f), fmaxf(p1.x + e.x, 0.f));
            o4[1] = make_float4(fmaxf(p1.y + e.y, 0.f), fmaxf(p1.z + e.z, 0.f),
                                fmaxf(p2.x + e.x, 0.f), fmaxf(p2.y + e.y, 0.f));
            o4[2] = make_float4(fmaxf(p2.z + e.z, 0.f), fmaxf(p3.x + e.x, 0.f),
                                fmaxf(p3.y + e.y, 0.f), fmaxf(p3.z + e.z, 0.f));

            if (write_targets) {
                int4 tv = targets[q];
                reinterpret_cast<float4*>(out + 3 * NSAMP)[q] =
                    make_float4((float)tv.x, (float)tv.y, (float)tv.z, (float)tv.w);
            }
        }
    }

    // ---- final arrive: last arrival resets counter for graph replay ----
    __syncthreads();
    if (tid == 0) {
        unsigned prev = atomicAdd(&g_bar, 1u);
        if (prev + 1u == 5u * GRID) atomicExch(&g_bar, 0u);
    }
}

// ---------------------------------------------------------------------------
extern "C" void kernel_launch(void* const* d_in, const int* in_sizes, int n_in,
                              void* d_out, int out_size) {
    const float*  eos_emb = (const float*) d_in[0];
    const int4*   sampled = (const int4*)  d_in[1];
    const int4*   targets = (const int4*)  d_in[2];
    const float4* tbl     = (const float4*)d_in[3];
    const float*  Wbin    = (const float*) d_in[4];
    const float*  Weos    = (const float*) d_in[5];
    const float*  beos    = (const float*) d_in[6];
    const float*  Wfc     = (const float*) d_in[7];
    const float*  bfc     = (const float*) d_in[8];
    float* out = (float*)d_out;

    int write_targets = (out_size >= 4 * NSAMP) ? 1 : 0;
    k_fused<<<GRID, 256>>>(eos_emb, sampled, targets, tbl,
                           Wbin, Weos, beos, Wfc, bfc, out, write_targets);
}

// round 14
// speedup vs baseline: 1.1212x; 1.1212x over previous
#include <cuda_runtime.h>

#define N_CHROM 23
#define BINS    5000
#define NB      16
#define NS      512
#define EOS_DIM 512
#define BIN_DIM 256
#define VOCAB   (N_CHROM * BINS)        // 115000
#define NSAMP   (N_CHROM * NB * NS)     // 188416
#define NQUAD   (NSAMP / 4)             // 47104
#define GRID    592                     // 148 SMs * 4 resident blocks
#define NWARPS  (GRID * 8)              // 4736
#define NUNITS  (VOCAB / 2)             // 57500 two-row units
#define EOS_B0  (GRID - 46)             // eos handled by high block ids
#define GWSHIFT 1600                    // remainder units -> bids 200..283

// ---- scratch (device globals) ----
__device__ float    g_M[3 * BIN_DIM];      // W_fc1 @ W_bin  [3,256]
__device__ float    g_Meos[3 * EOS_DIM];   // W_fc2 @ W_eos  [3,512]
__device__ float    g_cbias[4];
__device__ float4   g_E[NB * N_CHROM];
__device__ float4   g_P[VOCAB];
__device__ unsigned g_bar;                 // monotone barrier counter (zero-init)

__device__ __forceinline__ void grid_bar(unsigned target) {
    __syncthreads();
    if (threadIdx.x == 0) {
        __threadfence();
        unsigned prev = atomicAdd(&g_bar, 1u);
        if (prev + 1u < target) {
            while (*(volatile unsigned*)&g_bar < target) __nanosleep(32);
        }
        __threadfence();
    }
    __syncthreads();
}

__device__ __forceinline__ float dot8(float4 a, float4 b, float4 m, float4 mb) {
    return a.x*m.x + a.y*m.y + a.z*m.z + a.w*m.w
         + b.x*mb.x + b.y*mb.y + b.z*mb.z + b.w*mb.w;
}

__global__ void __launch_bounds__(256, 4)
k_fused(const float*  __restrict__ eos_emb,   // [16,23,512]
        const int4*   __restrict__ sampled,   // [23,16,512] as quads
        const int4*   __restrict__ targets,
        const float4* __restrict__ tbl,       // [115000,64] float4
        const float*  __restrict__ Wbin,      // [512,256]
        const float*  __restrict__ Weos,      // [512,512]
        const float*  __restrict__ beos,      // [512]
        const float*  __restrict__ Wfc,       // [3,1024]
        const float*  __restrict__ bfc,       // [3]
        float* __restrict__ out,
        int write_targets) {
    const int bid  = blockIdx.x;
    const int tid  = threadIdx.x;
    const int lane = tid & 31;
    const int warp = tid >> 5;

    // remapped sweep identity: remainder units land on prep/eos-free blocks
    int gw2 = bid * 8 + warp + GWSHIFT;
    if (gw2 >= NWARPS) gw2 -= NWARPS;

    __shared__ float  s[3][8][32];
    __shared__ float4 sM[3 * 64];

    // ---- early loads: first sweep unit in flight before/through prep ----
    float4 A0, A1, A2, A3;
    {
        const float4* b0 = tbl + (size_t)gw2 * 128;
        A0 = __ldcs(b0 + lane);
        A1 = __ldcs(b0 + 32 + lane);
        A2 = __ldcs(b0 + 64 + lane);
        A3 = __ldcs(b0 + 96 + lane);
    }

    // ================= Phase 0: fold the weight chain =================
    if (bid < 24) {
        bool is_eos = (bid < 16);
        int  e      = (is_eos ? bid * 32 : (bid - 16) * 32) + lane;
        int  stride = is_eos ? 512 : 256;
        const float* W = is_eos ? Weos : Wbin;
        int  fc     = is_eos ? 512 : 0;

        float a0 = 0.f, a1 = 0.f, a2 = 0.f;
        int dbeg = warp * 64;
#pragma unroll 16
        for (int d = dbeg; d < dbeg + 64; d++) {
            float w = W[d * stride + e];
            a0 += __ldg(&Wfc[fc + d])        * w;
            a1 += __ldg(&Wfc[1024 + fc + d]) * w;
            a2 += __ldg(&Wfc[2048 + fc + d]) * w;
        }
        s[0][warp][lane] = a0;
        s[1][warp][lane] = a1;
        s[2][warp][lane] = a2;
        __syncthreads();
#pragma unroll
        for (int off = 4; off; off >>= 1) {
            if (warp < off) {
                s[0][warp][lane] += s[0][warp + off][lane];
                s[1][warp][lane] += s[1][warp + off][lane];
                s[2][warp][lane] += s[2][warp + off][lane];
            }
            __syncthreads();
        }
        if (warp == 0) {
            if (is_eos) {
                g_Meos[e]        = s[0][0][lane];
                g_Meos[512 + e]  = s[1][0][lane];
                g_Meos[1024 + e] = s[2][0][lane];
            } else {
                g_M[e]           = s[0][0][lane];
                g_M[256 + e]     = s[1][0][lane];
                g_M[512 + e]     = s[2][0][lane];
            }
        }
    } else if (bid == 24 && tid < 32) {
        float a0 = 0.f, a1 = 0.f, a2 = 0.f;
#pragma unroll
        for (int d = lane; d < 512; d += 32) {
            float v = beos[d];
            a0 += Wfc[512 + d]        * v;
            a1 += Wfc[1024 + 512 + d] * v;
            a2 += Wfc[2048 + 512 + d] * v;
        }
#pragma unroll
        for (int o = 16; o; o >>= 1) {
            a0 += __shfl_down_sync(0xffffffffu, a0, o);
            a1 += __shfl_down_sync(0xffffffffu, a1, o);
            a2 += __shfl_down_sync(0xffffffffu, a2, o);
        }
        if (lane == 0) {
            g_cbias[0] = a0 + bfc[0];
            g_cbias[1] = a1 + bfc[1];
            g_cbias[2] = a2 + bfc[2];
        }
    }

    grid_bar(GRID);   // ---- barrier A: g_M / g_Meos / g_cbias ready ----

    if (tid < 192) sM[tid] = reinterpret_cast<const float4*>(g_M)[tid];
    __syncthreads();

    // ================= Phase 1a: eos dot (high blocks) =================
    if (bid >= EOS_B0) {
        int w = (bid - EOS_B0) * 8 + warp;   // 0..367 = b*23 + c
        const float4* row = reinterpret_cast<const float4*>(eos_emb + (size_t)w * EOS_DIM);
        const float4* M0  = reinterpret_cast<const float4*>(g_Meos);
        const float4* M1  = reinterpret_cast<const float4*>(g_Meos + EOS_DIM);
        const float4* M2  = reinterpret_cast<const float4*>(g_Meos + 2 * EOS_DIM);
        float s0 = 0.f, s1 = 0.f, s2 = 0.f;
#pragma unroll
        for (int i = lane; i < EOS_DIM / 4; i += 32) {
            float4 x = row[i];
            float4 m0 = M0[i], m1 = M1[i], m2 = M2[i];
            s0 += x.x*m0.x + x.y*m0.y + x.z*m0.z + x.w*m0.w;
            s1 += x.x*m1.x + x.y*m1.y + x.z*m1.z + x.w*m1.w;
            s2 += x.x*m2.x + x.y*m2.y + x.z*m2.z + x.w*m2.w;
        }
#pragma unroll
        for (int o = 16; o; o >>= 1) {
            s0 += __shfl_down_sync(0xffffffffu, s0, o);
            s1 += __shfl_down_sync(0xffffffffu, s1, o);
            s2 += __shfl_down_sync(0xffffffffu, s2, o);
        }
        if (lane == 0)
            g_E[w] = make_float4(s0 + g_cbias[0], s1 + g_cbias[1], s2 + g_cbias[2], 0.f);
    }

    // ===== Phase 1b: table sweep (round-4 shape, early-loaded prologue) =====
    {
        int p = gw2;
        while (true) {
            int  pn   = p + NWARPS;
            bool more = pn < NUNITS;
            float4 B0, B1, B2, B3;
            if (more) {
                const float4* nb = tbl + (size_t)pn * 128;
                B0 = __ldcs(nb + lane);           // prefetch next unit
                B1 = __ldcs(nb + 32 + lane);
                B2 = __ldcs(nb + 64 + lane);
                B3 = __ldcs(nb + 96 + lane);
            }
            // ---- row 0 of unit (A0,A1) ----
            float r0 = dot8(A0, A1, sM[lane],       sM[32 + lane]);
            float r1 = dot8(A0, A1, sM[64 + lane],  sM[96 + lane]);
            float r2 = dot8(A0, A1, sM[128 + lane], sM[160 + lane]);
#pragma unroll
            for (int o = 16; o; o >>= 1) {
                r0 += __shfl_xor_sync(0xffffffffu, r0, o);
                r1 += __shfl_xor_sync(0xffffffffu, r1, o);
                r2 += __shfl_xor_sync(0xffffffffu, r2, o);
            }
            // ---- row 1 of unit (A2,A3) ----
            float t0 = dot8(A2, A3, sM[lane],       sM[32 + lane]);
            float t1 = dot8(A2, A3, sM[64 + lane],  sM[96 + lane]);
            float t2 = dot8(A2, A3, sM[128 + lane], sM[160 + lane]);
#pragma unroll
            for (int o = 16; o; o >>= 1) {
                t0 += __shfl_xor_sync(0xffffffffu, t0, o);
                t1 += __shfl_xor_sync(0xffffffffu, t1, o);
                t2 += __shfl_xor_sync(0xffffffffu, t2, o);
            }
            if (lane < 2) {
                float4 v = (lane == 0) ? make_float4(r0, r1, r2, 0.f)
                                       : make_float4(t0, t1, t2, 0.f);
                g_P[2 * p + lane] = v;
            }
            if (!more) break;
            A0 = B0; A1 = B1; A2 = B2; A3 = B3;
            p = pn;
        }
    }

    grid_bar(2 * GRID);   // ---- barrier B: g_P / g_E ready ----

    // ================= Phase 2: gather + relu + emit ==================
    {
        int q = bid * 80 + tid;                 // 80 quads/block, coalesced
        if (tid < 80 && q < NQUAD) {
            int i = q * 4;
            int c = i / (NB * NS);
            int b = (i - c * (NB * NS)) / NS;

            int4 sv = sampled[q];
            int  vb = c * BINS;
            float4 p0 = g_P[vb + sv.x];
            float4 p1 = g_P[vb + sv.y];
            float4 p2 = g_P[vb + sv.z];
            float4 p3 = g_P[vb + sv.w];
            float4 e  = g_E[b * N_CHROM + c];

            float4* o4 = reinterpret_cast<float4*>(out + 12 * (size_t)q);
            o4[0] = make_float4(fmaxf(p0.x + e.x, 0.f), fmaxf(p0.y + e.y, 0.f),
                                fmaxf(p0.z + e.z, 0.f), fmaxf(p1.x + e.x, 0.f));
            o4[1] = make_float4(fmaxf(p1.y + e.y, 0.f), fmaxf(p1.z + e.z, 0.f),
                                fmaxf(p2.x + e.x, 0.f), fmaxf(p2.y + e.y, 0.f));
            o4[2] = make_float4(fmaxf(p2.z + e.z, 0.f), fmaxf(p3.x + e.x, 0.f),
                                fmaxf(p3.y + e.y, 0.f), fmaxf(p3.z + e.z, 0.f));

            if (write_targets) {
                int4 tv = targets[q];
                reinterpret_cast<float4*>(out + 3 * NSAMP)[q] =
                    make_float4((float)tv.x, (float)tv.y, (float)tv.z, (float)tv.w);
            }
        }
    }

    // ---- final arrive: last arrival resets counter for graph replay ----
    __syncthreads();
    if (tid == 0) {
        unsigned prev = atomicAdd(&g_bar, 1u);
        if (prev + 1u == 3u * GRID) atomicExch(&g_bar, 0u);
    }
}

// ---------------------------------------------------------------------------
extern "C" void kernel_launch(void* const* d_in, const int* in_sizes, int n_in,
                              void* d_out, int out_size) {
    const float*  eos_emb = (const float*) d_in[0];
    const int4*   sampled = (const int4*)  d_in[1];
    const int4*   targets = (const int4*)  d_in[2];
    const float4* tbl     = (const float4*)d_in[3];
    const float*  Wbin    = (const float*) d_in[4];
    const float*  Weos    = (const float*) d_in[5];
    const float*  beos    = (const float*) d_in[6];
    const float*  Wfc     = (const float*) d_in[7];
    const float*  bfc     = (const float*) d_in[8];
    float* out = (float*)d_out;

    int write_targets = (out_size >= 4 * NSAMP) ? 1 : 0;
    k_fused<<<GRID, 256>>>(eos_emb, sampled, targets, tbl,
                           Wbin, Weos, beos, Wfc, bfc, out, write_targets);
}

// round 15
// speedup vs baseline: 1.1862x; 1.0580x over previous
#include <cuda_runtime.h>

#define N_CHROM 23
#define BINS    5000
#define NB      16
#define NS      512
#define EOS_DIM 512
#define BIN_DIM 256
#define VOCAB   (N_CHROM * BINS)        // 115000
#define NSAMP   (N_CHROM * NB * NS)     // 188416
#define GRID    592                     // 148 SMs * 4 resident blocks
#define NWARPS  (GRID * 8)              // 4736
#define NUNITS  (VOCAB / 2)             // 57500 two-row units
#define EOS_B0  (GRID - 46)             // eos handled by high block ids

// ---- scratch (device globals) ----
__device__ float    g_M[3 * BIN_DIM];      // W_fc1 @ W_bin  [3,256]
__device__ float    g_Meos[3 * EOS_DIM];   // W_fc2 @ W_eos  [3,512]
__device__ float    g_cbias[4];
__device__ float4   g_E[NB * N_CHROM];
__device__ float4   g_P[VOCAB];
__device__ unsigned g_bar;                 // monotone barrier counter (zero-init)

__device__ __forceinline__ void grid_bar(unsigned target) {
    __syncthreads();
    if (threadIdx.x == 0) {
        __threadfence();
        unsigned prev = atomicAdd(&g_bar, 1u);
        if (prev + 1u < target) {
            while (*(volatile unsigned*)&g_bar < target) __nanosleep(32);
        }
        __threadfence();
    }
    __syncthreads();
}

__device__ __forceinline__ float dot8(float4 a, float4 b, float4 m, float4 mb) {
    return a.x*m.x + a.y*m.y + a.z*m.z + a.w*m.w
         + b.x*mb.x + b.y*mb.y + b.z*mb.z + b.w*mb.w;
}

__global__ void __launch_bounds__(256, 4)
k_fused(const float*  __restrict__ eos_emb,   // [16,23,512]
        const int4*   __restrict__ sampled,   // [23,16,512] as quads
        const int4*   __restrict__ targets,
        const float4* __restrict__ tbl,       // [115000,64] float4
        const float*  __restrict__ Wbin,      // [512,256]
        const float*  __restrict__ Weos,      // [512,512]
        const float*  __restrict__ beos,      // [512]
        const float*  __restrict__ Wfc,       // [3,1024]
        const float*  __restrict__ bfc,       // [3]
        float* __restrict__ out,
        int write_targets) {
    const int bid  = blockIdx.x;
    const int tid  = threadIdx.x;
    const int lane = tid & 31;
    const int warp = tid >> 5;

    __shared__ float  s[3][8][32];
    __shared__ float4 sM[3 * 64];

    // ================= Phase 0: fold the weight chain =================
    if (bid < 24) {
        bool is_eos = (bid < 16);
        int  e      = (is_eos ? bid * 32 : (bid - 16) * 32) + lane;
        int  stride = is_eos ? 512 : 256;
        const float* W = is_eos ? Weos : Wbin;
        int  fc     = is_eos ? 512 : 0;

        float a0 = 0.f, a1 = 0.f, a2 = 0.f;
        int dbeg = warp * 64;
#pragma unroll 16
        for (int d = dbeg; d < dbeg + 64; d++) {
            float w = W[d * stride + e];
            a0 += __ldg(&Wfc[fc + d])        * w;
            a1 += __ldg(&Wfc[1024 + fc + d]) * w;
            a2 += __ldg(&Wfc[2048 + fc + d]) * w;
        }
        s[0][warp][lane] = a0;
        s[1][warp][lane] = a1;
        s[2][warp][lane] = a2;
        __syncthreads();
#pragma unroll
        for (int off = 4; off; off >>= 1) {
            if (warp < off) {
                s[0][warp][lane] += s[0][warp + off][lane];
                s[1][warp][lane] += s[1][warp + off][lane];
                s[2][warp][lane] += s[2][warp + off][lane];
            }
            __syncthreads();
        }
        if (warp == 0) {
            if (is_eos) {
                g_Meos[e]        = s[0][0][lane];
                g_Meos[512 + e]  = s[1][0][lane];
                g_Meos[1024 + e] = s[2][0][lane];
            } else {
                g_M[e]           = s[0][0][lane];
                g_M[256 + e]     = s[1][0][lane];
                g_M[512 + e]     = s[2][0][lane];
            }
        }
    } else if (bid == 24 && tid < 32) {
        float a0 = 0.f, a1 = 0.f, a2 = 0.f;
#pragma unroll
        for (int d = lane; d < 512; d += 32) {
            float v = beos[d];
            a0 += Wfc[512 + d]        * v;
            a1 += Wfc[1024 + 512 + d] * v;
            a2 += Wfc[2048 + 512 + d] * v;
        }
#pragma unroll
        for (int o = 16; o; o >>= 1) {
            a0 += __shfl_down_sync(0xffffffffu, a0, o);
            a1 += __shfl_down_sync(0xffffffffu, a1, o);
            a2 += __shfl_down_sync(0xffffffffu, a2, o);
        }
        if (lane == 0) {
            g_cbias[0] = a0 + bfc[0];
            g_cbias[1] = a1 + bfc[1];
            g_cbias[2] = a2 + bfc[2];
        }
    }

    grid_bar(GRID);   // ---- barrier A: g_M / g_Meos / g_cbias ready ----

    if (tid < 192) sM[tid] = reinterpret_cast<const float4*>(g_M)[tid];
    __syncthreads();

    // ================= Phase 1a: eos dot (high blocks) =================
    if (bid >= EOS_B0) {
        int w = (bid - EOS_B0) * 8 + warp;   // 0..367 = b*23 + c
        const float4* row = reinterpret_cast<const float4*>(eos_emb + (size_t)w * EOS_DIM);
        const float4* M0  = reinterpret_cast<const float4*>(g_Meos);
        const float4* M1  = reinterpret_cast<const float4*>(g_Meos + EOS_DIM);
        const float4* M2  = reinterpret_cast<const float4*>(g_Meos + 2 * EOS_DIM);
        float s0 = 0.f, s1 = 0.f, s2 = 0.f;
#pragma unroll
        for (int i = lane; i < EOS_DIM / 4; i += 32) {
            float4 x = row[i];
            float4 m0 = M0[i], m1 = M1[i], m2 = M2[i];
            s0 += x.x*m0.x + x.y*m0.y + x.z*m0.z + x.w*m0.w;
            s1 += x.x*m1.x + x.y*m1.y + x.z*m1.z + x.w*m1.w;
            s2 += x.x*m2.x + x.y*m2.y + x.z*m2.z + x.w*m2.w;
        }
#pragma unroll
        for (int o = 16; o; o >>= 1) {
            s0 += __shfl_down_sync(0xffffffffu, s0, o);
            s1 += __shfl_down_sync(0xffffffffu, s1, o);
            s2 += __shfl_down_sync(0xffffffffu, s2, o);
        }
        if (lane == 0)
            g_E[w] = make_float4(s0 + g_cbias[0], s1 + g_cbias[1], s2 + g_cbias[2], 0.f);
    }

    // ===== Phase 1b: table sweep, software-pipelined (2 rows / unit) =====
    {
        const int gw = bid * 8 + warp;                // 0..4735, always < NUNITS
        int p = gw;

        float4 A0, A1, A2, A3;
        {
            const float4* b0 = tbl + (size_t)p * 128;
            A0 = __ldcs(b0 + lane);
            A1 = __ldcs(b0 + 32 + lane);
            A2 = __ldcs(b0 + 64 + lane);
            A3 = __ldcs(b0 + 96 + lane);
        }
        while (true) {
            int  pn   = p + NWARPS;
            bool more = pn < NUNITS;
            float4 B0, B1, B2, B3;
            if (more) {
                const float4* nb = tbl + (size_t)pn * 128;
                B0 = __ldcs(nb + lane);           // prefetch next unit
                B1 = __ldcs(nb + 32 + lane);
                B2 = __ldcs(nb + 64 + lane);
                B3 = __ldcs(nb + 96 + lane);
            }
            // ---- row 0 of unit (A0,A1) ----
            float r0 = dot8(A0, A1, sM[lane],       sM[32 + lane]);
            float r1 = dot8(A0, A1, sM[64 + lane],  sM[96 + lane]);
            float r2 = dot8(A0, A1, sM[128 + lane], sM[160 + lane]);
#pragma unroll
            for (int o = 16; o; o >>= 1) {
                r0 += __shfl_xor_sync(0xffffffffu, r0, o);
                r1 += __shfl_xor_sync(0xffffffffu, r1, o);
                r2 += __shfl_xor_sync(0xffffffffu, r2, o);
            }
            // ---- row 1 of unit (A2,A3) ----
            float t0 = dot8(A2, A3, sM[lane],       sM[32 + lane]);
            float t1 = dot8(A2, A3, sM[64 + lane],  sM[96 + lane]);
            float t2 = dot8(A2, A3, sM[128 + lane], sM[160 + lane]);
#pragma unroll
            for (int o = 16; o; o >>= 1) {
                t0 += __shfl_xor_sync(0xffffffffu, t0, o);
                t1 += __shfl_xor_sync(0xffffffffu, t1, o);
                t2 += __shfl_xor_sync(0xffffffffu, t2, o);
            }
            if (lane < 2) {
                float4 v = (lane == 0) ? make_float4(r0, r1, r2, 0.f)
                                       : make_float4(t0, t1, t2, 0.f);
                g_P[2 * p + lane] = v;
            }
            if (!more) break;
            A0 = B0; A1 = B1; A2 = B2; A3 = B3;
            p = pn;
        }
    }

    grid_bar(2 * GRID);   // ---- barrier B: g_P / g_E ready ----

    // ================= Phase 2: gather + relu + emit ==================
    {
        int q = bid * 80 + tid;                 // 80 quads/block, coalesced
        if (tid < 80 && q < NSAMP / 4) {
            int i = q * 4;
            int c = i / (NB * NS);
            int b = (i - c * (NB * NS)) / NS;

            int4 sv = sampled[q];
            int  vb = c * BINS;
            float4 p0 = g_P[vb + sv.x];
            float4 p1 = g_P[vb + sv.y];
            float4 p2 = g_P[vb + sv.z];
            float4 p3 = g_P[vb + sv.w];
            float4 e  = g_E[b * N_CHROM + c];

            float4* o4 = reinterpret_cast<float4*>(out + 12 * (size_t)q);
            o4[0] = make_float4(fmaxf(p0.x + e.x, 0.f), fmaxf(p0.y + e.y, 0.f),
                                fmaxf(p0.z + e.z, 0.f), fmaxf(p1.x + e.x, 0.f));
            o4[1] = make_float4(fmaxf(p1.y + e.y, 0.f), fmaxf(p1.z + e.z, 0.f),
                                fmaxf(p2.x + e.x, 0.f), fmaxf(p2.y + e.y, 0.f));
            o4[2] = make_float4(fmaxf(p2.z + e.z, 0.f), fmaxf(p3.x + e.x, 0.f),
                                fmaxf(p3.y + e.y, 0.f), fmaxf(p3.z + e.z, 0.f));

            if (write_targets) {
                int4 tv = targets[q];
                reinterpret_cast<float4*>(out + 3 * NSAMP)[q] =
                    make_float4((float)tv.x, (float)tv.y, (float)tv.z, (float)tv.w);
            }
        }
    }

    // ---- final arrive: last arrival resets counter for graph replay ----
    __syncthreads();
    if (tid == 0) {
        unsigned prev = atomicAdd(&g_bar, 1u);
        if (prev + 1u == 3u * GRID) atomicExch(&g_bar, 0u);
    }
}

// ---------------------------------------------------------------------------
extern "C" void kernel_launch(void* const* d_in, const int* in_sizes, int n_in,
                              void* d_out, int out_size) {
    const float*  eos_emb = (const float*) d_in[0];
    const int4*   sampled = (const int4*)  d_in[1];
    const int4*   targets = (const int4*)  d_in[2];
    const float4* tbl     = (const float4*)d_in[3];
    const float*  Wbin    = (const float*) d_in[4];
    const float*  Weos    = (const float*) d_in[5];
    const float*  beos    = (const float*) d_in[6];
    const float*  Wfc     = (const float*) d_in[7];
    const float*  bfc     = (const float*) d_in[8];
    float* out = (float*)d_out;

    int write_targets = (out_size >= 4 * NSAMP) ? 1 : 0;
    k_fused<<<GRID, 256>>>(eos_emb, sampled, targets, tbl,
                           Wbin, Weos, beos, Wfc, bfc, out, write_targets);
}